// round 1
// baseline (speedup 1.0000x reference)
#include <cuda_runtime.h>
#include <cstdint>

#define NN   100000
#define EE   1600000
#define HH   128
#define GG   256
#define CC   25
#define LL   3
#define FIN  10
#define BN_EPS 1e-5f

// ---------------- scratch (device globals; no allocation) ----------------
__device__ float g_h[(size_t)NN * HH];
__device__ float g_hw[(size_t)NN * HH];
__device__ float g_agg[(size_t)NN * HH];
__device__ float g_deg[NN];
__device__ float g_dinv[NN];
__device__ float g_psum[GG * HH];
__device__ float g_pmax[GG * HH];
__device__ int   g_cnt[GG];

// vector float reduction to global (sm_90+)
__device__ __forceinline__ void red_add_v4(float* addr, float a, float b, float c, float d) {
    asm volatile("red.global.add.v4.f32 [%0], {%1, %2, %3, %4};"
                 :: "l"(addr), "f"(a), "f"(b), "f"(c), "f"(d) : "memory");
}

// ---------------- degree ----------------
__global__ void k_deg_init() {
    int i = blockIdx.x * blockDim.x + threadIdx.x;
    if (i < NN) g_deg[i] = 1.0f;   // self loop
}
__global__ void k_deg_acc(const int* __restrict__ rows) {
    int e = blockIdx.x * blockDim.x + threadIdx.x;
    if (e < EE) atomicAdd(&g_deg[rows[e]], 1.0f);
}
__global__ void k_deg_inv() {
    int i = blockIdx.x * blockDim.x + threadIdx.x;
    if (i < NN) g_dinv[i] = rsqrtf(g_deg[i]);
}

// ---------------- projection: h = relu(x @ Wp + bp) ----------------
__global__ void k_proj(const float* __restrict__ x, const float* __restrict__ Wp,
                       const float* __restrict__ bp) {
    __shared__ float sW[FIN * HH];
    __shared__ float sb[HH];
    int t = threadIdx.x;  // 128
    for (int i = t; i < FIN * HH; i += HH) sW[i] = Wp[i];
    sb[t] = bp[t];
    __syncthreads();
    int n0 = blockIdx.x * 64;
    for (int i = 0; i < 64; i++) {
        int n = n0 + i;
        if (n >= NN) break;
        float acc = sb[t];
#pragma unroll
        for (int k = 0; k < FIN; k++)
            acc = fmaf(x[(size_t)n * FIN + k], sW[k * HH + t], acc);
        g_h[(size_t)n * HH + t] = fmaxf(acc, 0.0f);
    }
}

// ---------------- GEMM: g_hw = g_h @ W (128x128) ----------------
// block = 256 threads (8 warps), 32 rows/block, warp handles 4 rows,
// lane computes columns [4*lane, 4*lane+4).
__global__ void k_gemm(const float* __restrict__ W) {
    extern __shared__ float smem[];
    float* Ws = smem;                 // 128*128
    float* hs = smem + HH * HH;       // 8*4*128
    for (int i = threadIdx.x; i < HH * HH / 4; i += 256)
        ((float4*)Ws)[i] = ((const float4*)W)[i];

    int warp = threadIdx.x >> 5, lane = threadIdx.x & 31;
    int row0 = blockIdx.x * 32 + warp * 4;
    float* hrow = hs + warp * 4 * HH;
#pragma unroll
    for (int r = 0; r < 4; r++) {
        int row = row0 + r;
        float4 v = (row < NN) ? ((const float4*)(g_h + (size_t)row * HH))[lane]
                              : make_float4(0.f, 0.f, 0.f, 0.f);
        ((float4*)(hrow + r * HH))[lane] = v;
    }
    __syncthreads();

    float4 a0 = {0,0,0,0}, a1 = {0,0,0,0}, a2 = {0,0,0,0}, a3 = {0,0,0,0};
#pragma unroll 8
    for (int k = 0; k < HH; k++) {
        float4 w = ((float4*)(Ws + k * HH))[lane];
        float h0 = hrow[0 * HH + k], h1 = hrow[1 * HH + k];
        float h2 = hrow[2 * HH + k], h3 = hrow[3 * HH + k];
        a0.x = fmaf(h0, w.x, a0.x); a0.y = fmaf(h0, w.y, a0.y);
        a0.z = fmaf(h0, w.z, a0.z); a0.w = fmaf(h0, w.w, a0.w);
        a1.x = fmaf(h1, w.x, a1.x); a1.y = fmaf(h1, w.y, a1.y);
        a1.z = fmaf(h1, w.z, a1.z); a1.w = fmaf(h1, w.w, a1.w);
        a2.x = fmaf(h2, w.x, a2.x); a2.y = fmaf(h2, w.y, a2.y);
        a2.z = fmaf(h2, w.z, a2.z); a2.w = fmaf(h2, w.w, a2.w);
        a3.x = fmaf(h3, w.x, a3.x); a3.y = fmaf(h3, w.y, a3.y);
        a3.z = fmaf(h3, w.z, a3.z); a3.w = fmaf(h3, w.w, a3.w);
    }
#pragma unroll
    for (int r = 0; r < 4; r++) {
        int row = row0 + r;
        if (row < NN) {
            float4 a = (r == 0) ? a0 : (r == 1) ? a1 : (r == 2) ? a2 : a3;
            ((float4*)(g_hw + (size_t)row * HH))[lane] = a;
        }
    }
}

// ---------------- agg init with self loop: agg = hw * dinv^2 ----------------
__global__ void k_agg_init() {
    int t = blockIdx.x * blockDim.x + threadIdx.x;   // NN*32 float4 groups
    if (t >= NN * 32) return;
    int n = t >> 5;
    float d = g_dinv[n];
    float w = d * d;
    float4 v = ((const float4*)g_hw)[t];
    float4 o = make_float4(v.x * w, v.y * w, v.z * w, v.w * w);
    ((float4*)g_agg)[t] = o;
}

// ---------------- scatter: agg[r] += hw[c] * dinv[r]*dinv[c] ----------------
// one warp per edge, lane = float4 group
__global__ void k_scatter(const int* __restrict__ rows, const int* __restrict__ cols) {
    int t = blockIdx.x * blockDim.x + threadIdx.x;
    int e = t >> 5;
    if (e >= EE) return;
    int fg = t & 31;
    int r = rows[e], c = cols[e];
    float w = g_dinv[r] * g_dinv[c];
    float4 v = ((const float4*)(g_hw + (size_t)c * HH))[fg];
    red_add_v4(g_agg + (size_t)r * HH + fg * 4, v.x * w, v.y * w, v.z * w, v.w * w);
}

// ---------------- BN + ReLU epilogue: g_h = relu(bn(agg + bc)) ----------------
__global__ void k_bn_relu(const float* __restrict__ bc, const float* __restrict__ gamma,
                          const float* __restrict__ beta, const float* __restrict__ mean,
                          const float* __restrict__ var) {
    int t = blockIdx.x * blockDim.x + threadIdx.x;   // NN*32 float4 groups
    if (t >= NN * 32) return;
    int fg = t & 31;
    int f = fg * 4;
    float4 a = ((const float4*)g_agg)[t];
    float4 o;
    {
        float s = rsqrtf(var[f + 0] + BN_EPS) * gamma[f + 0];
        o.x = fmaxf((a.x + bc[f + 0] - mean[f + 0]) * s + beta[f + 0], 0.f);
    }
    {
        float s = rsqrtf(var[f + 1] + BN_EPS) * gamma[f + 1];
        o.y = fmaxf((a.y + bc[f + 1] - mean[f + 1]) * s + beta[f + 1], 0.f);
    }
    {
        float s = rsqrtf(var[f + 2] + BN_EPS) * gamma[f + 2];
        o.z = fmaxf((a.z + bc[f + 2] - mean[f + 2]) * s + beta[f + 2], 0.f);
    }
    {
        float s = rsqrtf(var[f + 3] + BN_EPS) * gamma[f + 3];
        o.w = fmaxf((a.w + bc[f + 3] - mean[f + 3]) * s + beta[f + 3], 0.f);
    }
    ((float4*)g_h)[t] = o;
}

// ---------------- pooling ----------------
__global__ void k_zero_pool() {
    int i = blockIdx.x * blockDim.x + threadIdx.x;
    if (i < GG * HH) { g_psum[i] = 0.0f; g_pmax[i] = 0.0f; }
    if (i < GG) g_cnt[i] = 0;
}

// block: 128 threads (thread=feature), 32 contiguous nodes; batch is sorted so
// register-accumulate per graph segment, atomic flush only on boundary.
__global__ void k_pool(const int* __restrict__ batch) {
    int f = threadIdx.x;
    int n0 = blockIdx.x * 32;
    int curg = batch[n0];
    float s = 0.f, m = 0.f;
    int c = 0;
    for (int i = 0; i < 32; i++) {
        int n = n0 + i;
        if (n >= NN) break;
        int g = batch[n];
        if (g != curg) {
            atomicAdd(&g_psum[curg * HH + f], s);
            atomicMax((int*)&g_pmax[curg * HH + f], __float_as_int(m));
            if (f == 0) atomicAdd(&g_cnt[curg], c);
            s = 0.f; m = 0.f; c = 0; curg = g;
        }
        float v = g_h[(size_t)n * HH + f];
        s += v;
        m = fmaxf(m, v);
        c++;
    }
    atomicAdd(&g_psum[curg * HH + f], s);
    atomicMax((int*)&g_pmax[curg * HH + f], __float_as_int(m));
    if (f == 0) atomicAdd(&g_cnt[curg], c);
}

// ---------------- final MLP: out = relu(g @ W1 + b1) @ W2 + b2 ----------------
__global__ void k_mlp(const float* __restrict__ W1, const float* __restrict__ b1,
                      const float* __restrict__ W2, const float* __restrict__ b2,
                      float* __restrict__ out) {
    __shared__ float gv[2 * HH];
    __shared__ float hid[HH];
    int g = blockIdx.x, t = threadIdx.x;  // 128
    float cntf = fmaxf((float)g_cnt[g], 1.0f);
    gv[t] = g_psum[g * HH + t] / cntf;
    gv[HH + t] = g_pmax[g * HH + t];
    __syncthreads();
    float acc = b1[t];
#pragma unroll 8
    for (int k = 0; k < 2 * HH; k++)
        acc = fmaf(gv[k], W1[k * HH + t], acc);
    hid[t] = fmaxf(acc, 0.0f);
    __syncthreads();
    if (t < CC) {
        float o = b2[t];
#pragma unroll 8
        for (int c = 0; c < HH; c++)
            o = fmaf(hid[c], W2[c * CC + t], o);
        out[g * CC + t] = o;
    }
}

// ---------------- launch ----------------
extern "C" void kernel_launch(void* const* d_in, const int* in_sizes, int n_in,
                              void* d_out, int out_size) {
    const float* x     = (const float*)d_in[0];
    const int*   ei    = (const int*)d_in[1];      // [2, E] flattened
    const int*   batch = (const int*)d_in[2];
    const float* Wp    = (const float*)d_in[3];
    const float* bp    = (const float*)d_in[4];
    const float* Wc    = (const float*)d_in[5];    // [L, H, H]
    const float* bc    = (const float*)d_in[6];    // [L, H]
    const float* bn_g  = (const float*)d_in[7];
    const float* bn_b  = (const float*)d_in[8];
    const float* bn_m  = (const float*)d_in[9];
    const float* bn_v  = (const float*)d_in[10];
    const float* W1    = (const float*)d_in[11];
    const float* b1    = (const float*)d_in[12];
    const float* W2    = (const float*)d_in[13];
    const float* b2    = (const float*)d_in[14];
    float* out = (float*)d_out;

    const int* rows = ei;        // targets (aggregation index)
    const int* cols = ei + EE;   // sources (gather index)

    static bool attr_set = false;
    // setting every call is also fine/deterministic; guard only saves a driver call
    cudaFuncSetAttribute(k_gemm, cudaFuncAttributeMaxDynamicSharedMemorySize,
                         (HH * HH + 8 * 4 * HH) * (int)sizeof(float));
    attr_set = true;

    // degree + dinv
    k_deg_init<<<(NN + 255) / 256, 256>>>();
    k_deg_acc<<<(EE + 255) / 256, 256>>>(rows);
    k_deg_inv<<<(NN + 255) / 256, 256>>>();

    // pooling buffers reset
    k_zero_pool<<<(GG * HH + 255) / 256, 256>>>();

    // input projection
    k_proj<<<(NN + 63) / 64, 128>>>(x, Wp, bp);

    const int smem = (HH * HH + 8 * 4 * HH) * (int)sizeof(float);
    const int nv4 = NN * 32;
    for (int l = 0; l < LL; l++) {
        k_gemm<<<(NN + 31) / 32, 256, smem>>>(Wc + (size_t)l * HH * HH);
        k_agg_init<<<(nv4 + 255) / 256, 256>>>();
        k_scatter<<<(EE * 32 + 255) / 256, 256>>>(rows, cols);
        k_bn_relu<<<(nv4 + 255) / 256, 256>>>(bc + l * HH, bn_g + l * HH,
                                              bn_b + l * HH, bn_m + l * HH,
                                              bn_v + l * HH);
    }

    // pooling
    k_pool<<<NN / 32, 128>>>(batch);

    // final MLP
    k_mlp<<<GG, 128>>>(W1, b1, W2, b2, out);
}

// round 2
// speedup vs baseline: 1.8327x; 1.8327x over previous
#include <cuda_runtime.h>
#include <cstdint>

#define NN   100000
#define EE   1600000
#define HH   128
#define GG   256
#define CC   25
#define LL   3
#define FIN  10
#define BN_EPS 1e-5f

#define SCAN_BS 1024
#define SCAN_NB ((NN + SCAN_BS - 1) / SCAN_BS)   // 98

// ---------------- scratch (device globals; no allocation) ----------------
__device__ float g_h[(size_t)NN * HH];
__device__ float g_hw[(size_t)NN * HH];
__device__ int   g_deg[NN];
__device__ float g_dinv[NN];
__device__ int   g_csr_start[NN + 1];
__device__ int   g_cursor[NN];
__device__ int   g_csr_col[EE];
__device__ int   g_blocksum[SCAN_NB];
__device__ float g_bnA[HH];
__device__ float g_bnB[HH];
__device__ float g_psum[GG * HH];
__device__ float g_pmax[GG * HH];
__device__ int   g_cnt[GG];

// ---------------- init: zero degree + pooling buffers ----------------
__global__ void k_init() {
    int i = blockIdx.x * blockDim.x + threadIdx.x;
    if (i < NN) g_deg[i] = 0;
    if (i < GG * HH) { g_psum[i] = 0.0f; g_pmax[i] = 0.0f; }
    if (i < GG) g_cnt[i] = 0;
}

__global__ void k_deg_acc(const int* __restrict__ rows) {
    int e = blockIdx.x * blockDim.x + threadIdx.x;
    if (e < EE) atomicAdd(&g_deg[rows[e]], 1);
}

// ---------------- scan (3-phase exclusive prefix over degree) ----------------
__device__ __forceinline__ int block_scan_inclusive(int v, int* sh, int nwarps) {
    int lane = threadIdx.x & 31, wid = threadIdx.x >> 5;
#pragma unroll
    for (int o = 1; o < 32; o <<= 1) {
        int n = __shfl_up_sync(0xffffffffu, v, o);
        if (lane >= o) v += n;
    }
    if (lane == 31) sh[wid] = v;
    __syncthreads();
    if (wid == 0) {
        int w = (lane < nwarps) ? sh[lane] : 0;
#pragma unroll
        for (int o = 1; o < 32; o <<= 1) {
            int n = __shfl_up_sync(0xffffffffu, w, o);
            if (lane >= o) w += n;
        }
        if (lane < nwarps) sh[lane] = w;
    }
    __syncthreads();
    if (wid > 0) v += sh[wid - 1];
    return v;
}

// phase 1: per-block inclusive scan of deg -> csr_start[i+1], block totals
__global__ void k_scan1() {
    __shared__ int sh[32];
    int i = blockIdx.x * SCAN_BS + threadIdx.x;
    int v = (i < NN) ? g_deg[i] : 0;
    int inc = block_scan_inclusive(v, sh, 32);
    if (i < NN) g_csr_start[i + 1] = inc;
    if (threadIdx.x == SCAN_BS - 1) g_blocksum[blockIdx.x] = inc;
    if (i == 0) g_csr_start[0] = 0;
}

// phase 2: scan block totals (SCAN_NB <= 128), store exclusive offsets
__global__ void k_scan2() {
    __shared__ int sh[32];
    int t = threadIdx.x;  // 128
    int v = (t < SCAN_NB) ? g_blocksum[t] : 0;
    int inc = block_scan_inclusive(v, sh, 4);
    if (t < SCAN_NB) g_blocksum[t] = inc - v;  // exclusive
}

// phase 3: add offsets, init cursor, compute dinv
__global__ void k_scan3() {
    int i = blockIdx.x * blockDim.x + threadIdx.x;
    if (i >= NN) return;
    int off = g_blocksum[i / SCAN_BS];
    int s = g_csr_start[i + 1] + off;
    g_csr_start[i + 1] = s;
    g_cursor[i] = s - g_deg[i];
    g_dinv[i] = rsqrtf(1.0f + (float)g_deg[i]);
}

// ---------------- CSR fill ----------------
__global__ void k_fill(const int* __restrict__ rows, const int* __restrict__ cols) {
    int e = blockIdx.x * blockDim.x + threadIdx.x;
    if (e >= EE) return;
    int r = rows[e];
    int pos = atomicAdd(&g_cursor[r], 1);
    g_csr_col[pos] = cols[e];
}

// ---------------- projection: h = relu(x @ Wp + bp) ----------------
__global__ void k_proj(const float* __restrict__ x, const float* __restrict__ Wp,
                       const float* __restrict__ bp) {
    __shared__ float sW[FIN * HH];
    __shared__ float sb[HH];
    int t = threadIdx.x;  // 128
    for (int i = t; i < FIN * HH; i += HH) sW[i] = Wp[i];
    sb[t] = bp[t];
    __syncthreads();
    int n0 = blockIdx.x * 64;
    for (int i = 0; i < 64; i++) {
        int n = n0 + i;
        if (n >= NN) break;
        float acc = sb[t];
#pragma unroll
        for (int k = 0; k < FIN; k++)
            acc = fmaf(x[(size_t)n * FIN + k], sW[k * HH + t], acc);
        g_h[(size_t)n * HH + t] = fmaxf(acc, 0.0f);
    }
}

// ---------------- GEMM: g_hw = g_h @ W (128x128) ----------------
__global__ void k_gemm(const float* __restrict__ W) {
    extern __shared__ float smem[];
    float* Ws = smem;                 // 128*128
    float* hs = smem + HH * HH;       // 8*4*128
    for (int i = threadIdx.x; i < HH * HH / 4; i += 256)
        ((float4*)Ws)[i] = ((const float4*)W)[i];

    int warp = threadIdx.x >> 5, lane = threadIdx.x & 31;
    int row0 = blockIdx.x * 32 + warp * 4;
    float* hrow = hs + warp * 4 * HH;
#pragma unroll
    for (int r = 0; r < 4; r++) {
        int row = row0 + r;
        float4 v = (row < NN) ? ((const float4*)(g_h + (size_t)row * HH))[lane]
                              : make_float4(0.f, 0.f, 0.f, 0.f);
        ((float4*)(hrow + r * HH))[lane] = v;
    }
    __syncthreads();

    float4 a0 = {0,0,0,0}, a1 = {0,0,0,0}, a2 = {0,0,0,0}, a3 = {0,0,0,0};
#pragma unroll 8
    for (int k = 0; k < HH; k++) {
        float4 w = ((float4*)(Ws + k * HH))[lane];
        float h0 = hrow[0 * HH + k], h1 = hrow[1 * HH + k];
        float h2 = hrow[2 * HH + k], h3 = hrow[3 * HH + k];
        a0.x = fmaf(h0, w.x, a0.x); a0.y = fmaf(h0, w.y, a0.y);
        a0.z = fmaf(h0, w.z, a0.z); a0.w = fmaf(h0, w.w, a0.w);
        a1.x = fmaf(h1, w.x, a1.x); a1.y = fmaf(h1, w.y, a1.y);
        a1.z = fmaf(h1, w.z, a1.z); a1.w = fmaf(h1, w.w, a1.w);
        a2.x = fmaf(h2, w.x, a2.x); a2.y = fmaf(h2, w.y, a2.y);
        a2.z = fmaf(h2, w.z, a2.z); a2.w = fmaf(h2, w.w, a2.w);
        a3.x = fmaf(h3, w.x, a3.x); a3.y = fmaf(h3, w.y, a3.y);
        a3.z = fmaf(h3, w.z, a3.z); a3.w = fmaf(h3, w.w, a3.w);
    }
#pragma unroll
    for (int r = 0; r < 4; r++) {
        int row = row0 + r;
        if (row < NN) {
            float4 a = (r == 0) ? a0 : (r == 1) ? a1 : (r == 2) ? a2 : a3;
            ((float4*)(g_hw + (size_t)row * HH))[lane] = a;
        }
    }
}

// ---------------- bn prep: A = gamma*rsqrt(var+eps); B = (bc-mean)*A+beta ----------------
__global__ void k_bnprep(const float* __restrict__ bc, const float* __restrict__ gamma,
                         const float* __restrict__ beta, const float* __restrict__ mean,
                         const float* __restrict__ var) {
    int t = threadIdx.x;  // 128
    float A = gamma[t] * rsqrtf(var[t] + BN_EPS);
    g_bnA[t] = A;
    g_bnB[t] = (bc[t] - mean[t]) * A + beta[t];
}

// ---------------- fused gather + self loop + BN + ReLU ----------------
// warp per node; lane owns float4 group (32 lanes x 16B = 512B row)
__global__ void k_gather_bn() {
    int node = blockIdx.x * 4 + (threadIdx.x >> 5);
    if (node >= NN) return;
    int lane = threadIdx.x & 31;

    float dr = g_dinv[node];
    float4 acc = ((const float4*)(g_hw + (size_t)node * HH))[lane];
    float ws = dr * dr;
    acc.x *= ws; acc.y *= ws; acc.z *= ws; acc.w *= ws;

    int s = g_csr_start[node], e = g_csr_start[node + 1];
    int i = s;
    for (; i + 1 < e; i += 2) {
        int c0 = g_csr_col[i];
        int c1 = g_csr_col[i + 1];
        float w0 = dr * g_dinv[c0];
        float w1 = dr * g_dinv[c1];
        float4 v0 = ((const float4*)(g_hw + (size_t)c0 * HH))[lane];
        float4 v1 = ((const float4*)(g_hw + (size_t)c1 * HH))[lane];
        acc.x = fmaf(v0.x, w0, acc.x); acc.y = fmaf(v0.y, w0, acc.y);
        acc.z = fmaf(v0.z, w0, acc.z); acc.w = fmaf(v0.w, w0, acc.w);
        acc.x = fmaf(v1.x, w1, acc.x); acc.y = fmaf(v1.y, w1, acc.y);
        acc.z = fmaf(v1.z, w1, acc.z); acc.w = fmaf(v1.w, w1, acc.w);
    }
    if (i < e) {
        int c = g_csr_col[i];
        float w = dr * g_dinv[c];
        float4 v = ((const float4*)(g_hw + (size_t)c * HH))[lane];
        acc.x = fmaf(v.x, w, acc.x); acc.y = fmaf(v.y, w, acc.y);
        acc.z = fmaf(v.z, w, acc.z); acc.w = fmaf(v.w, w, acc.w);
    }

    float4 A = ((const float4*)g_bnA)[lane];
    float4 B = ((const float4*)g_bnB)[lane];
    float4 o;
    o.x = fmaxf(fmaf(acc.x, A.x, B.x), 0.f);
    o.y = fmaxf(fmaf(acc.y, A.y, B.y), 0.f);
    o.z = fmaxf(fmaf(acc.z, A.z, B.z), 0.f);
    o.w = fmaxf(fmaf(acc.w, A.w, B.w), 0.f);
    ((float4*)(g_h + (size_t)node * HH))[lane] = o;
}

// ---------------- pooling (batch sorted: register segments, flush on boundary) ----------------
__global__ void k_pool(const int* __restrict__ batch) {
    int f = threadIdx.x;
    int n0 = blockIdx.x * 32;
    int curg = batch[n0];
    float s = 0.f, m = 0.f;
    int c = 0;
    for (int i = 0; i < 32; i++) {
        int n = n0 + i;
        if (n >= NN) break;
        int g = batch[n];
        if (g != curg) {
            atomicAdd(&g_psum[curg * HH + f], s);
            atomicMax((int*)&g_pmax[curg * HH + f], __float_as_int(m));
            if (f == 0) atomicAdd(&g_cnt[curg], c);
            s = 0.f; m = 0.f; c = 0; curg = g;
        }
        float v = g_h[(size_t)n * HH + f];
        s += v;
        m = fmaxf(m, v);
        c++;
    }
    atomicAdd(&g_psum[curg * HH + f], s);
    atomicMax((int*)&g_pmax[curg * HH + f], __float_as_int(m));
    if (f == 0) atomicAdd(&g_cnt[curg], c);
}

// ---------------- final MLP ----------------
__global__ void k_mlp(const float* __restrict__ W1, const float* __restrict__ b1,
                      const float* __restrict__ W2, const float* __restrict__ b2,
                      float* __restrict__ out) {
    __shared__ float gv[2 * HH];
    __shared__ float hid[HH];
    int g = blockIdx.x, t = threadIdx.x;  // 128
    float cntf = fmaxf((float)g_cnt[g], 1.0f);
    gv[t] = g_psum[g * HH + t] / cntf;
    gv[HH + t] = g_pmax[g * HH + t];
    __syncthreads();
    float acc = b1[t];
#pragma unroll 8
    for (int k = 0; k < 2 * HH; k++)
        acc = fmaf(gv[k], W1[k * HH + t], acc);
    hid[t] = fmaxf(acc, 0.0f);
    __syncthreads();
    if (t < CC) {
        float o = b2[t];
#pragma unroll 8
        for (int c = 0; c < HH; c++)
            o = fmaf(hid[c], W2[c * CC + t], o);
        out[g * CC + t] = o;
    }
}

// ---------------- launch ----------------
extern "C" void kernel_launch(void* const* d_in, const int* in_sizes, int n_in,
                              void* d_out, int out_size) {
    const float* x     = (const float*)d_in[0];
    const int*   ei    = (const int*)d_in[1];      // [2, E] flattened
    const int*   batch = (const int*)d_in[2];
    const float* Wp    = (const float*)d_in[3];
    const float* bp    = (const float*)d_in[4];
    const float* Wc    = (const float*)d_in[5];    // [L, H, H]
    const float* bc    = (const float*)d_in[6];    // [L, H]
    const float* bn_g  = (const float*)d_in[7];
    const float* bn_b  = (const float*)d_in[8];
    const float* bn_m  = (const float*)d_in[9];
    const float* bn_v  = (const float*)d_in[10];
    const float* W1    = (const float*)d_in[11];
    const float* b1    = (const float*)d_in[12];
    const float* W2    = (const float*)d_in[13];
    const float* b2    = (const float*)d_in[14];
    float* out = (float*)d_out;

    const int* rows = ei;        // targets (aggregation index)
    const int* cols = ei + EE;   // sources (gather index)

    cudaFuncSetAttribute(k_gemm, cudaFuncAttributeMaxDynamicSharedMemorySize,
                         (HH * HH + 8 * 4 * HH) * (int)sizeof(float));

    // init + degree + CSR build
    k_init<<<(NN + 255) / 256, 256>>>();
    k_deg_acc<<<(EE + 255) / 256, 256>>>(rows);
    k_scan1<<<SCAN_NB, SCAN_BS>>>();
    k_scan2<<<1, 128>>>();
    k_scan3<<<(NN + 255) / 256, 256>>>();
    k_fill<<<(EE + 255) / 256, 256>>>(rows, cols);

    // input projection (overlaps with CSR build on other SMs is fine; same stream order)
    k_proj<<<(NN + 63) / 64, 128>>>(x, Wp, bp);

    const int smem = (HH * HH + 8 * 4 * HH) * (int)sizeof(float);
    for (int l = 0; l < LL; l++) {
        k_bnprep<<<1, 128>>>(bc + l * HH, bn_g + l * HH, bn_b + l * HH,
                             bn_m + l * HH, bn_v + l * HH);
        k_gemm<<<(NN + 31) / 32, 256, smem>>>(Wc + (size_t)l * HH * HH);
        k_gather_bn<<<(NN + 3) / 4, 128>>>();
    }

    // pooling + MLP
    k_pool<<<NN / 32, 128>>>(batch);
    k_mlp<<<GG, 128>>>(W1, b1, W2, b2, out);
}